// round 7
// baseline (speedup 1.0000x reference)
#include <cuda_runtime.h>

#define NN  100000      // nodes
#define FIN 512         // input features
#define HID 16          // hidden
#define NC  40          // classes
#define CSR_CAP 192     // per-node bucket capacity (deg ~ Binom, mean 32, sd 5.7)

// ---------------- device scratch --------------------------------------------
__device__ int   g_is64;
__device__ int   g_cur [NN];               // atomic cursors -> degree
__device__ int   g_deg [NN];               // clamped degree
__device__ float g_dinv[NN];
__device__ int   g_csr[(size_t)NN * CSR_CAP];   // 76.8MB bucket CSR
__device__ float g_h [(size_t)NN * HID];   // raw x@W1 (side stream)
__device__ float g_hs[(size_t)NN * HID];   // h1*dinv, later a2
__device__ float g_ys[(size_t)NN * HID];   // relu(out1)*dinv

// ---------------- init: zero cursors + detect index dtype ---------------------
__global__ __launch_bounds__(256) void init_k(const unsigned int* __restrict__ w,
                                              int E, int N) {
    int i = blockIdx.x * 256 + threadIdx.x;
    if (i < N) g_cur[i] = 0;
    if (blockIdx.x == 0) {
        __shared__ unsigned int sh[256];
        unsigned int acc = 0;
        int n = min(E, 4096);
        for (int j = threadIdx.x; j < n; j += 256) acc |= w[2 * j + 1];
        sh[threadIdx.x] = acc;
        __syncthreads();
        for (int s = 128; s > 0; s >>= 1) {
            if (threadIdx.x < s) sh[threadIdx.x] |= sh[threadIdx.x + s];
            __syncthreads();
        }
        if (threadIdx.x == 0) g_is64 = (sh[0] == 0u) ? 1 : 0;
    }
}

// ---------------- bucket CSR fill (single pass, 2 edges/thread) ---------------
__global__ __launch_bounds__(256) void csr_fill(const void* __restrict__ ei, int E) {
    int i = blockIdx.x * 256 + threadIdx.x;
    int e = 2 * i;
    if (e >= E) return;
    int s0, d0, s1 = -1, d1 = -1;
    if (g_is64) {
        const long long* p = (const long long*)ei;
        if (e + 1 < E) {
            longlong2 sp = *(const longlong2*)(p + e);
            longlong2 dp = *(const longlong2*)(p + E + e);
            s0 = (int)sp.x; s1 = (int)sp.y;
            d0 = (int)dp.x; d1 = (int)dp.y;
        } else {
            s0 = (int)p[e]; d0 = (int)p[e + E];
        }
    } else {
        const int* p = (const int*)ei;
        if (e + 1 < E) {
            int2 sp = *(const int2*)(p + e);
            int2 dp = *(const int2*)(p + E + e);
            s0 = sp.x; s1 = sp.y;
            d0 = dp.x; d1 = dp.y;
        } else {
            s0 = p[e]; d0 = p[e + E];
        }
    }
    int p0 = atomicAdd(&g_cur[d0], 1);
    if (p0 < CSR_CAP) g_csr[(size_t)d0 * CSR_CAP + p0] = s0;
    if (s1 >= 0 || d1 >= 0) {
        if (e + 1 < E) {
            int p1 = atomicAdd(&g_cur[d1], 1);
            if (p1 < CSR_CAP) g_csr[(size_t)d1 * CSR_CAP + p1] = s1;
        }
    }
}

// ---------------- packed f32x2 helpers ----------------------------------------
__device__ __forceinline__ unsigned long long pack2(float v) {
    unsigned long long r;
    unsigned int u = __float_as_uint(v);
    asm("mov.b64 %0, {%1, %1};" : "=l"(r) : "r"(u));
    return r;
}
__device__ __forceinline__ unsigned long long ffma2(unsigned long long a,
                                                    unsigned long long b,
                                                    unsigned long long c) {
    unsigned long long d;
    asm("fma.rn.f32x2 %0, %1, %2, %3;" : "=l"(d) : "l"(a), "l"(b), "l"(c));
    return d;
}
__device__ __forceinline__ float2 unpack2(unsigned long long v) {
    unsigned int lo, hi;
    asm("mov.b64 {%0, %1}, %2;" : "=r"(lo), "=r"(hi) : "l"(v));
    return make_float2(__uint_as_float(lo), __uint_as_float(hi));
}

// ---------------- GEMM1 (raw): h = x @ W1  (side stream) ----------------------
__global__ __launch_bounds__(128) void gemm1(const float* __restrict__ x,
                                             const float* __restrict__ W1, int N) {
    __shared__ ulonglong2 Ws[FIN * 4];   // 512 x 16 floats = 32KB
    const ulonglong2* Wg = (const ulonglong2*)W1;
    for (int i = threadIdx.x; i < FIN * 4; i += 128) Ws[i] = Wg[i];
    __syncthreads();

    int base = blockIdx.x * 512 + threadIdx.x * 4;
    if (base >= N) return;

    unsigned long long acc[4][8];
#pragma unroll
    for (int r = 0; r < 4; r++)
#pragma unroll
        for (int p = 0; p < 8; p++) acc[r][p] = 0ull;

    int row[4];
    const float* xp[4];
#pragma unroll
    for (int r = 0; r < 4; r++) {
        row[r] = min(base + r, N - 1);
        xp[r] = x + (size_t)row[r] * FIN;
    }

    for (int k = 0; k < FIN; k += 4) {
        float xv[4][4];
#pragma unroll
        for (int r = 0; r < 4; r++)
            *(float4*)xv[r] = *(const float4*)(xp[r] + k);
#pragma unroll
        for (int j = 0; j < 4; j++) {
            ulonglong2 wa = Ws[(k + j) * 4 + 0];
            ulonglong2 wb = Ws[(k + j) * 4 + 1];
            ulonglong2 wc = Ws[(k + j) * 4 + 2];
            ulonglong2 wd = Ws[(k + j) * 4 + 3];
#pragma unroll
            for (int r = 0; r < 4; r++) {
                unsigned long long px = pack2(xv[r][j]);
                acc[r][0] = ffma2(px, wa.x, acc[r][0]);
                acc[r][1] = ffma2(px, wa.y, acc[r][1]);
                acc[r][2] = ffma2(px, wb.x, acc[r][2]);
                acc[r][3] = ffma2(px, wb.y, acc[r][3]);
                acc[r][4] = ffma2(px, wc.x, acc[r][4]);
                acc[r][5] = ffma2(px, wc.y, acc[r][5]);
                acc[r][6] = ffma2(px, wd.x, acc[r][6]);
                acc[r][7] = ffma2(px, wd.y, acc[r][7]);
            }
        }
    }

#pragma unroll
    for (int r = 0; r < 4; r++) {
        if (base + r >= N) break;
        int rw = row[r];
        float* hp = g_h + (size_t)rw * HID;
#pragma unroll
        for (int p = 0; p < 8; p++) {
            float2 v = unpack2(acc[r][p]);
            hp[2 * p + 0] = v.x;
            hp[2 * p + 1] = v.y;
        }
    }
}

// ---------------- prep (after join): deg, dinv, hs = h * dinv -----------------
__global__ __launch_bounds__(256) void prep(int N) {
    int i = blockIdx.x * 256 + threadIdx.x;
    if (i >= N) return;
    int c = g_cur[i];
    float dv = rsqrtf((float)(c + 1));   // +1 self-loop
    g_dinv[i] = dv;
    g_deg[i] = min(c, CSR_CAP);
    const float4* hp = (const float4*)(g_h + (size_t)i * HID);
    float4* op = (float4*)(g_hs + (size_t)i * HID);
#pragma unroll
    for (int p = 0; p < 4; p++) {
        float4 v = hp[p];
        v.x *= dv; v.y *= dv; v.z *= dv; v.w *= dv;
        op[p] = v;
    }
}

// ---------------- CSR aggregation: 8 lanes/dst, float2 slices -----------------
// Layer 1: ys = relu(dinv*(self + sum) + b1) * dinv
__global__ __launch_bounds__(256) void agg1(const float* __restrict__ b1, int N) {
    int t = threadIdx.x;
    int d = blockIdx.x * 32 + (t >> 3);
    if (d >= N) return;
    int part = t & 7;
    const float2* tbl = (const float2*)g_hs + part;   // row s at tbl[s*8]

    float2 acc = tbl[(size_t)d * 8];   // self-loop
    const int* cp = g_csr + (size_t)d * CSR_CAP;
    int deg = g_deg[d];

    int e = 0;
    int deg8 = deg & ~7;
    for (; e < deg8; e += 8) {
        int s0 = cp[e],     s1 = cp[e + 1], s2 = cp[e + 2], s3 = cp[e + 3];
        int s4 = cp[e + 4], s5 = cp[e + 5], s6 = cp[e + 6], s7 = cp[e + 7];
        float2 v0 = tbl[(size_t)s0 * 8];
        float2 v1 = tbl[(size_t)s1 * 8];
        float2 v2 = tbl[(size_t)s2 * 8];
        float2 v3 = tbl[(size_t)s3 * 8];
        float2 v4 = tbl[(size_t)s4 * 8];
        float2 v5 = tbl[(size_t)s5 * 8];
        float2 v6 = tbl[(size_t)s6 * 8];
        float2 v7 = tbl[(size_t)s7 * 8];
        acc.x += (v0.x + v1.x) + (v2.x + v3.x) + (v4.x + v5.x) + (v6.x + v7.x);
        acc.y += (v0.y + v1.y) + (v2.y + v3.y) + (v4.y + v5.y) + (v6.y + v7.y);
    }
    for (; e < deg; e++) {
        float2 v = tbl[(size_t)cp[e] * 8];
        acc.x += v.x; acc.y += v.y;
    }

    float dv = g_dinv[d];
    float2 bb = ((const float2*)b1)[part];
    float2 y;
    y.x = fmaxf(fmaf(acc.x, dv, bb.x), 0.0f) * dv;
    y.y = fmaxf(fmaf(acc.y, dv, bb.y), 0.0f) * dv;
    ((float2*)g_ys)[(size_t)d * 8 + part] = y;
}

// Layer 2: a2 = dinv*(self + sum)  -> g_hs (consumed by final_k)
__global__ __launch_bounds__(256) void agg2(int N) {
    int t = threadIdx.x;
    int d = blockIdx.x * 32 + (t >> 3);
    if (d >= N) return;
    int part = t & 7;
    const float2* tbl = (const float2*)g_ys + part;

    float2 acc = tbl[(size_t)d * 8];   // self-loop
    const int* cp = g_csr + (size_t)d * CSR_CAP;
    int deg = g_deg[d];

    int e = 0;
    int deg8 = deg & ~7;
    for (; e < deg8; e += 8) {
        int s0 = cp[e],     s1 = cp[e + 1], s2 = cp[e + 2], s3 = cp[e + 3];
        int s4 = cp[e + 4], s5 = cp[e + 5], s6 = cp[e + 6], s7 = cp[e + 7];
        float2 v0 = tbl[(size_t)s0 * 8];
        float2 v1 = tbl[(size_t)s1 * 8];
        float2 v2 = tbl[(size_t)s2 * 8];
        float2 v3 = tbl[(size_t)s3 * 8];
        float2 v4 = tbl[(size_t)s4 * 8];
        float2 v5 = tbl[(size_t)s5 * 8];
        float2 v6 = tbl[(size_t)s6 * 8];
        float2 v7 = tbl[(size_t)s7 * 8];
        acc.x += (v0.x + v1.x) + (v2.x + v3.x) + (v4.x + v5.x) + (v6.x + v7.x);
        acc.y += (v0.y + v1.y) + (v2.y + v3.y) + (v4.y + v5.y) + (v6.y + v7.y);
    }
    for (; e < deg; e++) {
        float2 v = tbl[(size_t)cp[e] * 8];
        acc.x += v.x; acc.y += v.y;
    }

    float dv = g_dinv[d];
    ((float2*)g_hs)[(size_t)d * 8 + part] = make_float2(acc.x * dv, acc.y * dv);
}

// ---------------- final: logits = a2@W2 + b2 ; log_softmax --------------------
__global__ __launch_bounds__(128) void final_k(const float* __restrict__ W2,
                                               const float* __restrict__ b2,
                                               float* __restrict__ out_lsm,
                                               float* __restrict__ out_logits,
                                               int N, int write_logits) {
    __shared__ float Ws[HID * NC];
    __shared__ float Bs[NC];
    for (int i = threadIdx.x; i < HID * NC; i += 128) Ws[i] = W2[i];
    if (threadIdx.x < NC) Bs[threadIdx.x] = b2[threadIdx.x];
    __syncthreads();

    int node = blockIdx.x * 128 + threadIdx.x;
    if (node >= N) return;

    const float* ap = g_hs + (size_t)node * HID;
    float a[HID];
#pragma unroll
    for (int j = 0; j < HID; j++) a[j] = ap[j];

    float z[NC];
#pragma unroll
    for (int c = 0; c < NC; c++) z[c] = Bs[c];
#pragma unroll
    for (int j = 0; j < HID; j++) {
        float aj = a[j];
#pragma unroll
        for (int c = 0; c < NC; c++) z[c] = fmaf(aj, Ws[j * NC + c], z[c]);
    }

    float m = z[0];
#pragma unroll
    for (int c = 1; c < NC; c++) m = fmaxf(m, z[c]);
    float s = 0.0f;
#pragma unroll
    for (int c = 0; c < NC; c++) s += __expf(z[c] - m);
    float lse = m + __logf(s);

    float* ol = out_lsm + (size_t)node * NC;
#pragma unroll
    for (int c = 0; c < NC; c++) ol[c] = z[c] - lse;
    if (write_logits) {
        float* og = out_logits + (size_t)node * NC;
#pragma unroll
        for (int c = 0; c < NC; c++) og[c] = z[c];
    }
}

// ---------------- launch ------------------------------------------------------
extern "C" void kernel_launch(void* const* d_in, const int* in_sizes, int n_in,
                              void* d_out, int out_size) {
    const float* x  = (const float*)d_in[0];
    const void*  ei = d_in[1];
    const float* W1 = (const float*)d_in[2];
    const float* b1 = (const float*)d_in[3];
    const float* W2 = (const float*)d_in[4];
    const float* b2 = (const float*)d_in[5];

    int E = in_sizes[1] / 2;
    int N = in_sizes[0] / FIN;
    if (N > NN) N = NN;

    float* out = (float*)d_out;
    int write_logits = (out_size >= 2 * N * NC) ? 1 : 0;
    float* out_lsm = out;
    float* out_logits = out + (size_t)N * NC;

    int nb_nodes = (N + 255) / 256;
    int nb_pairs = ((E + 1) / 2 + 255) / 256;
    int nb_agg   = (N + 31) / 32;

    // lazy side-stream setup (created on the uncaptured correctness call)
    static cudaStream_t s2 = 0;
    static cudaEvent_t evF = 0, evJ = 0;
    static int inited = 0;
    if (!inited) {
        if (cudaStreamCreateWithFlags(&s2, cudaStreamNonBlocking) != cudaSuccess) s2 = 0;
        if (s2) {
            if (cudaEventCreateWithFlags(&evF, cudaEventDisableTiming) != cudaSuccess ||
                cudaEventCreateWithFlags(&evJ, cudaEventDisableTiming) != cudaSuccess) {
                s2 = 0;
            }
        }
        inited = 1;
    }
    int fork = (s2 != 0);

    // branch B: dense projection (independent of edge pipeline)
    if (fork) {
        cudaEventRecord(evF, 0);
        cudaStreamWaitEvent(s2, evF, 0);
        gemm1<<<(N + 511) / 512, 128, 0, s2>>>(x, W1, N);
        cudaEventRecord(evJ, s2);
    } else {
        gemm1<<<(N + 511) / 512, 128>>>(x, W1, N);
    }

    // branch A: bucket-CSR build (default stream)
    init_k<<<nb_nodes, 256>>>((const unsigned int*)ei, E, N);
    csr_fill<<<nb_pairs, 256>>>(ei, E);

    // join
    if (fork) cudaStreamWaitEvent(0, evJ, 0);
    prep<<<nb_nodes, 256>>>(N);
    agg1<<<nb_agg, 256>>>(b1, N);
    agg2<<<nb_agg, 256>>>(N);
    final_k<<<(N + 127) / 128, 128>>>(W2, b2, out_lsm, out_logits, N, write_logits);
}

// round 10
// speedup vs baseline: 1.0139x; 1.0139x over previous
#include <cuda_runtime.h>

#define NN  100000      // nodes
#define FIN 512         // input features
#define HID 16          // hidden
#define NC  40          // classes
#define CSR_CAP 192     // per-node bucket capacity (deg ~ Binom(3.2M,1e-5): mean 32, sd 5.7)

// ---------------- device scratch --------------------------------------------
__device__ int   g_is64;
__device__ int   g_cur [NN];               // atomic cursors -> degree
__device__ int   g_deg [NN];               // clamped degree
__device__ float g_dinv[NN];
__device__ int   g_csr[(size_t)NN * CSR_CAP];   // 76.8MB bucket CSR
__device__ float g_h [(size_t)NN * HID];   // raw x@W1 (side stream)
__device__ float g_hs[(size_t)NN * HID];   // h1*dinv, later a2
__device__ float g_ys[(size_t)NN * HID];   // relu(out1)*dinv

// ---------------- init: zero cursors + detect index dtype ---------------------
__global__ __launch_bounds__(256) void init_k(const unsigned int* __restrict__ w,
                                              int E, int N) {
    int i = blockIdx.x * 256 + threadIdx.x;
    if (i < N) g_cur[i] = 0;
    if (blockIdx.x == 0) {
        __shared__ unsigned int sh[256];
        unsigned int acc = 0;
        int n = min(E, 4096);
        for (int j = threadIdx.x; j < n; j += 256) acc |= w[2 * j + 1];
        sh[threadIdx.x] = acc;
        __syncthreads();
        for (int s = 128; s > 0; s >>= 1) {
            if (threadIdx.x < s) sh[threadIdx.x] |= sh[threadIdx.x + s];
            __syncthreads();
        }
        if (threadIdx.x == 0) g_is64 = (sh[0] == 0u) ? 1 : 0;
    }
}

// ---------------- bucket CSR fill (single pass) -------------------------------
__global__ __launch_bounds__(256) void csr_fill(const void* __restrict__ ei, int E) {
    int e = blockIdx.x * 256 + threadIdx.x;
    if (e >= E) return;
    int s, d;
    if (g_is64) {
        const long long* p = (const long long*)ei;
        s = (int)p[e];
        d = (int)p[e + E];
    } else {
        const int* p = (const int*)ei;
        s = p[e];
        d = p[e + E];
    }
    int pos = atomicAdd(&g_cur[d], 1);
    if (pos < CSR_CAP) g_csr[(size_t)d * CSR_CAP + pos] = s;
}

// ---------------- packed f32x2 helpers ----------------------------------------
__device__ __forceinline__ unsigned long long pack2(float v) {
    unsigned long long r;
    unsigned int u = __float_as_uint(v);
    asm("mov.b64 %0, {%1, %1};" : "=l"(r) : "r"(u));
    return r;
}
__device__ __forceinline__ unsigned long long ffma2(unsigned long long a,
                                                    unsigned long long b,
                                                    unsigned long long c) {
    unsigned long long d;
    asm("fma.rn.f32x2 %0, %1, %2, %3;" : "=l"(d) : "l"(a), "l"(b), "l"(c));
    return d;
}
__device__ __forceinline__ float2 unpack2(unsigned long long v) {
    unsigned int lo, hi;
    asm("mov.b64 {%0, %1}, %2;" : "=r"(lo), "=r"(hi) : "l"(v));
    return make_float2(__uint_as_float(lo), __uint_as_float(hi));
}

// ---------------- GEMM1 (raw): h = x @ W1  (side stream) ----------------------
__global__ __launch_bounds__(128) void gemm1(const float* __restrict__ x,
                                             const float* __restrict__ W1, int N) {
    __shared__ ulonglong2 Ws[FIN * 4];   // 512 x 16 floats = 32KB
    const ulonglong2* Wg = (const ulonglong2*)W1;
    for (int i = threadIdx.x; i < FIN * 4; i += 128) Ws[i] = Wg[i];
    __syncthreads();

    int base = blockIdx.x * 512 + threadIdx.x * 4;
    if (base >= N) return;

    unsigned long long acc[4][8];
#pragma unroll
    for (int r = 0; r < 4; r++)
#pragma unroll
        for (int p = 0; p < 8; p++) acc[r][p] = 0ull;

    int row[4];
    const float* xp[4];
#pragma unroll
    for (int r = 0; r < 4; r++) {
        row[r] = min(base + r, N - 1);
        xp[r] = x + (size_t)row[r] * FIN;
    }

    for (int k = 0; k < FIN; k += 4) {
        float xv[4][4];
#pragma unroll
        for (int r = 0; r < 4; r++)
            *(float4*)xv[r] = *(const float4*)(xp[r] + k);
#pragma unroll
        for (int j = 0; j < 4; j++) {
            ulonglong2 wa = Ws[(k + j) * 4 + 0];
            ulonglong2 wb = Ws[(k + j) * 4 + 1];
            ulonglong2 wc = Ws[(k + j) * 4 + 2];
            ulonglong2 wd = Ws[(k + j) * 4 + 3];
#pragma unroll
            for (int r = 0; r < 4; r++) {
                unsigned long long px = pack2(xv[r][j]);
                acc[r][0] = ffma2(px, wa.x, acc[r][0]);
                acc[r][1] = ffma2(px, wa.y, acc[r][1]);
                acc[r][2] = ffma2(px, wb.x, acc[r][2]);
                acc[r][3] = ffma2(px, wb.y, acc[r][3]);
                acc[r][4] = ffma2(px, wc.x, acc[r][4]);
                acc[r][5] = ffma2(px, wc.y, acc[r][5]);
                acc[r][6] = ffma2(px, wd.x, acc[r][6]);
                acc[r][7] = ffma2(px, wd.y, acc[r][7]);
            }
        }
    }

#pragma unroll
    for (int r = 0; r < 4; r++) {
        if (base + r >= N) break;
        int rw = row[r];
        float* hp = g_h + (size_t)rw * HID;
#pragma unroll
        for (int p = 0; p < 8; p++) {
            float2 v = unpack2(acc[r][p]);
            hp[2 * p + 0] = v.x;
            hp[2 * p + 1] = v.y;
        }
    }
}

// ---------------- prep (after join): deg, dinv, hs = h * dinv -----------------
__global__ __launch_bounds__(256) void prep(int N) {
    int i = blockIdx.x * 256 + threadIdx.x;
    if (i >= N) return;
    int c = g_cur[i];
    float dv = rsqrtf((float)(c + 1));   // +1 self-loop
    g_dinv[i] = dv;
    g_deg[i] = min(c, CSR_CAP);
    const float4* hp = (const float4*)(g_h + (size_t)i * HID);
    float4* op = (float4*)(g_hs + (size_t)i * HID);
#pragma unroll
    for (int p = 0; p < 4; p++) {
        float4 v = hp[p];
        v.x *= dv; v.y *= dv; v.z *= dv; v.w *= dv;
        op[p] = v;
    }
}

// ---------------- CSR aggregation (R6 shape: 4 lanes/dst, float4, unroll 8) ---
// Layer 1: ys = relu(dinv*(self + sum) + b1) * dinv
__global__ __launch_bounds__(256) void agg1(const float* __restrict__ b1, int N) {
    int t = threadIdx.x;
    int d = blockIdx.x * 64 + (t >> 2);
    if (d >= N) return;
    int part = t & 3;
    const float* tbl = g_hs + part * 4;

    float4 acc = *(const float4*)(tbl + (size_t)d * HID);   // self-loop
    const int* cp = g_csr + (size_t)d * CSR_CAP;
    int deg = g_deg[d];

    int e = 0;
    int deg8 = deg & ~7;
    for (; e < deg8; e += 8) {
        int s0 = cp[e],     s1 = cp[e + 1], s2 = cp[e + 2], s3 = cp[e + 3];
        int s4 = cp[e + 4], s5 = cp[e + 5], s6 = cp[e + 6], s7 = cp[e + 7];
        float4 v0 = *(const float4*)(tbl + (size_t)s0 * HID);
        float4 v1 = *(const float4*)(tbl + (size_t)s1 * HID);
        float4 v2 = *(const float4*)(tbl + (size_t)s2 * HID);
        float4 v3 = *(const float4*)(tbl + (size_t)s3 * HID);
        float4 v4 = *(const float4*)(tbl + (size_t)s4 * HID);
        float4 v5 = *(const float4*)(tbl + (size_t)s5 * HID);
        float4 v6 = *(const float4*)(tbl + (size_t)s6 * HID);
        float4 v7 = *(const float4*)(tbl + (size_t)s7 * HID);
        acc.x += (v0.x + v1.x) + (v2.x + v3.x) + (v4.x + v5.x) + (v6.x + v7.x);
        acc.y += (v0.y + v1.y) + (v2.y + v3.y) + (v4.y + v5.y) + (v6.y + v7.y);
        acc.z += (v0.z + v1.z) + (v2.z + v3.z) + (v4.z + v5.z) + (v6.z + v7.z);
        acc.w += (v0.w + v1.w) + (v2.w + v3.w) + (v4.w + v5.w) + (v6.w + v7.w);
    }
    for (; e < deg; e++) {
        int s = cp[e];
        float4 v = *(const float4*)(tbl + (size_t)s * HID);
        acc.x += v.x; acc.y += v.y; acc.z += v.z; acc.w += v.w;
    }

    float dv = g_dinv[d];
    float4 bb = *(const float4*)(b1 + part * 4);
    float4 y;
    y.x = fmaxf(fmaf(acc.x, dv, bb.x), 0.0f) * dv;
    y.y = fmaxf(fmaf(acc.y, dv, bb.y), 0.0f) * dv;
    y.z = fmaxf(fmaf(acc.z, dv, bb.z), 0.0f) * dv;
    y.w = fmaxf(fmaf(acc.w, dv, bb.w), 0.0f) * dv;
    *(float4*)(g_ys + (size_t)d * HID + part * 4) = y;
}

// Layer 2: a2 = dinv*(self + sum)  -> g_hs (consumed by final_k)
__global__ __launch_bounds__(256) void agg2(int N) {
    int t = threadIdx.x;
    int d = blockIdx.x * 64 + (t >> 2);
    if (d >= N) return;
    int part = t & 3;
    const float* tbl = g_ys + part * 4;

    float4 acc = *(const float4*)(tbl + (size_t)d * HID);   // self-loop
    const int* cp = g_csr + (size_t)d * CSR_CAP;
    int deg = g_deg[d];

    int e = 0;
    int deg8 = deg & ~7;
    for (; e < deg8; e += 8) {
        int s0 = cp[e],     s1 = cp[e + 1], s2 = cp[e + 2], s3 = cp[e + 3];
        int s4 = cp[e + 4], s5 = cp[e + 5], s6 = cp[e + 6], s7 = cp[e + 7];
        float4 v0 = *(const float4*)(tbl + (size_t)s0 * HID);
        float4 v1 = *(const float4*)(tbl + (size_t)s1 * HID);
        float4 v2 = *(const float4*)(tbl + (size_t)s2 * HID);
        float4 v3 = *(const float4*)(tbl + (size_t)s3 * HID);
        float4 v4 = *(const float4*)(tbl + (size_t)s4 * HID);
        float4 v5 = *(const float4*)(tbl + (size_t)s5 * HID);
        float4 v6 = *(const float4*)(tbl + (size_t)s6 * HID);
        float4 v7 = *(const float4*)(tbl + (size_t)s7 * HID);
        acc.x += (v0.x + v1.x) + (v2.x + v3.x) + (v4.x + v5.x) + (v6.x + v7.x);
        acc.y += (v0.y + v1.y) + (v2.y + v3.y) + (v4.y + v5.y) + (v6.y + v7.y);
        acc.z += (v0.z + v1.z) + (v2.z + v3.z) + (v4.z + v5.z) + (v6.z + v7.z);
        acc.w += (v0.w + v1.w) + (v2.w + v3.w) + (v4.w + v5.w) + (v6.w + v7.w);
    }
    for (; e < deg; e++) {
        int s = cp[e];
        float4 v = *(const float4*)(tbl + (size_t)s * HID);
        acc.x += v.x; acc.y += v.y; acc.z += v.z; acc.w += v.w;
    }

    float dv = g_dinv[d];
    float4 a;
    a.x = acc.x * dv; a.y = acc.y * dv; a.z = acc.z * dv; a.w = acc.w * dv;
    *(float4*)(g_hs + (size_t)d * HID + part * 4) = a;
}

// ---------------- final: logits = a2@W2 + b2 ; log_softmax --------------------
__global__ __launch_bounds__(128) void final_k(const float* __restrict__ W2,
                                               const float* __restrict__ b2,
                                               float* __restrict__ out_lsm,
                                               float* __restrict__ out_logits,
                                               int N, int write_logits) {
    __shared__ float Ws[HID * NC];
    __shared__ float Bs[NC];
    for (int i = threadIdx.x; i < HID * NC; i += 128) Ws[i] = W2[i];
    if (threadIdx.x < NC) Bs[threadIdx.x] = b2[threadIdx.x];
    __syncthreads();

    int node = blockIdx.x * 128 + threadIdx.x;
    if (node >= N) return;

    const float* ap = g_hs + (size_t)node * HID;
    float a[HID];
#pragma unroll
    for (int j = 0; j < HID; j++) a[j] = ap[j];

    float z[NC];
#pragma unroll
    for (int c = 0; c < NC; c++) z[c] = Bs[c];
#pragma unroll
    for (int j = 0; j < HID; j++) {
        float aj = a[j];
#pragma unroll
        for (int c = 0; c < NC; c++) z[c] = fmaf(aj, Ws[j * NC + c], z[c]);
    }

    float m = z[0];
#pragma unroll
    for (int c = 1; c < NC; c++) m = fmaxf(m, z[c]);
    float s = 0.0f;
#pragma unroll
    for (int c = 0; c < NC; c++) s += __expf(z[c] - m);
    float lse = m + __logf(s);

    float* ol = out_lsm + (size_t)node * NC;
#pragma unroll
    for (int c = 0; c < NC; c++) ol[c] = z[c] - lse;
    if (write_logits) {
        float* og = out_logits + (size_t)node * NC;
#pragma unroll
        for (int c = 0; c < NC; c++) og[c] = z[c];
    }
}

// ---------------- launch ------------------------------------------------------
extern "C" void kernel_launch(void* const* d_in, const int* in_sizes, int n_in,
                              void* d_out, int out_size) {
    const float* x  = (const float*)d_in[0];
    const void*  ei = d_in[1];
    const float* W1 = (const float*)d_in[2];
    const float* b1 = (const float*)d_in[3];
    const float* W2 = (const float*)d_in[4];
    const float* b2 = (const float*)d_in[5];

    int E = in_sizes[1] / 2;
    int N = in_sizes[0] / FIN;
    if (N > NN) N = NN;

    float* out = (float*)d_out;
    int write_logits = (out_size >= 2 * N * NC) ? 1 : 0;
    float* out_lsm = out;
    float* out_logits = out + (size_t)N * NC;

    int nb_nodes = (N + 255) / 256;
    int nb_edges = (E + 255) / 256;
    int nb_agg   = (N + 63) / 64;

    // lazy side-stream setup (created on the uncaptured correctness call)
    static cudaStream_t s2 = 0;
    static cudaEvent_t evF = 0, evJ = 0;
    static int inited = 0;
    if (!inited) {
        if (cudaStreamCreateWithFlags(&s2, cudaStreamNonBlocking) != cudaSuccess) s2 = 0;
        if (s2) {
            if (cudaEventCreateWithFlags(&evF, cudaEventDisableTiming) != cudaSuccess ||
                cudaEventCreateWithFlags(&evJ, cudaEventDisableTiming) != cudaSuccess) {
                s2 = 0;
            }
        }
        inited = 1;
    }
    int fork = (s2 != 0);

    // branch B: dense projection (independent of edge pipeline)
    if (fork) {
        cudaEventRecord(evF, 0);
        cudaStreamWaitEvent(s2, evF, 0);
        gemm1<<<(N + 511) / 512, 128, 0, s2>>>(x, W1, N);
        cudaEventRecord(evJ, s2);
    } else {
        gemm1<<<(N + 511) / 512, 128>>>(x, W1, N);
    }

    // branch A: bucket-CSR build (default stream)
    init_k<<<nb_nodes, 256>>>((const unsigned int*)ei, E, N);
    csr_fill<<<nb_edges, 256>>>(ei, E);

    // join
    if (fork) cudaStreamWaitEvent(0, evJ, 0);
    prep<<<nb_nodes, 256>>>(N);
    agg1<<<nb_agg, 256>>>(b1, N);
    agg2<<<nb_agg, 256>>>(N);
    final_k<<<(N + 127) / 128, 128>>>(W2, b2, out_lsm, out_logits, N, write_logits);
}